// round 1
// baseline (speedup 1.0000x reference)
#include <cuda_runtime.h>
#include <cstdint>

#define N_NODES 4096
#define N_EDGES 65536
#define LDIM 64
#define KDIM 256
#define EDIM 6
#define KL (KDIM*LDIM)   /* 16384 */

// ---------------- scratch (device globals; no runtime allocation) ----------------
__device__ float g_W3p[LDIM*KL];                 // permuted W3: [i][k*64+o]  (4 MB)
__device__ float g_h1[(size_t)N_EDGES*KDIM];     // 64 MB
__device__ float g_h [(size_t)N_EDGES*KDIM];     // 64 MB
__device__ float g_P [(size_t)N_NODES*KL];       // 256 MB
__device__ float g_x1 [N_NODES*LDIM];
__device__ float g_xb3[N_NODES*LDIM];
__device__ float g_agg[N_NODES*LDIM];
__device__ int   g_deg[N_NODES];
__device__ int   g_off[N_NODES+1];
__device__ int   g_cur[N_NODES];
__device__ int   g_csr[N_EDGES];

// ---------------- helpers ----------------
__device__ __forceinline__ float gelu_f(float x){
    return 0.5f * x * (1.0f + erff(x * 0.70710678118654752440f));
}
__device__ __forceinline__ uint32_t f2tf(float x){
    uint32_t u; asm("cvt.rna.tf32.f32 %0, %1;" : "=r"(u) : "f"(x)); return u;
}
__device__ __forceinline__ void mma8(float* c, const uint32_t* a, const uint32_t* b){
    asm volatile(
        "mma.sync.aligned.m16n8k8.row.col.f32.tf32.tf32.f32 "
        "{%0,%1,%2,%3}, {%4,%5,%6,%7}, {%8,%9}, {%0,%1,%2,%3};\n"
        : "+f"(c[0]), "+f"(c[1]), "+f"(c[2]), "+f"(c[3])
        : "r"(a[0]), "r"(a[1]), "r"(a[2]), "r"(a[3]), "r"(b[0]), "r"(b[1]));
}

// ---------------- init / CSR build ----------------
__global__ void k_init(){
    int idx = blockIdx.x*256 + threadIdx.x;        // 262144 threads
    g_agg[idx] = 0.f;
    if (idx < N_NODES) g_deg[idx] = 0;
}
__global__ void k_zero_agg(){
    int idx = blockIdx.x*256 + threadIdx.x;
    g_agg[idx] = 0.f;
}
__global__ void k_deg(const int* __restrict__ ei){
    int e = blockIdx.x*256 + threadIdx.x;
    atomicAdd(&g_deg[ei[e]], 1);
}
__global__ void k_scan(){                          // 1 block, 1024 threads, 4 elems each
    __shared__ int wsum[32];
    int t = threadIdx.x, lane = t & 31, w = t >> 5;
    int d0 = g_deg[t*4+0], d1 = g_deg[t*4+1], d2 = g_deg[t*4+2], d3 = g_deg[t*4+3];
    int s0 = d0, s1 = s0+d1, s2 = s1+d2, s3 = s2+d3;
    int tot = s3;
    int v = tot;
    #pragma unroll
    for (int off=1; off<32; off<<=1){ int u = __shfl_up_sync(0xffffffffu, v, off); if (lane>=off) v += u; }
    if (lane == 31) wsum[w] = v;
    __syncthreads();
    if (w == 0){
        int s = wsum[lane];
        #pragma unroll
        for (int off=1; off<32; off<<=1){ int u = __shfl_up_sync(0xffffffffu, s, off); if (lane>=off) s += u; }
        wsum[lane] = s;
    }
    __syncthreads();
    int base = v - tot + (w ? wsum[w-1] : 0);      // exclusive base of this thread's chunk
    g_off[t*4+0] = base;      g_cur[t*4+0] = base;
    g_off[t*4+1] = base+s0;   g_cur[t*4+1] = base+s0;
    g_off[t*4+2] = base+s1;   g_cur[t*4+2] = base+s1;
    g_off[t*4+3] = base+s2;   g_cur[t*4+3] = base+s2;
    if (t == 1023) g_off[N_NODES] = base + tot;
}
__global__ void k_fill(const int* __restrict__ ei){
    int e = blockIdx.x*256 + threadIdx.x;
    int s = ei[e];
    int pos = atomicAdd(&g_cur[s], 1);
    g_csr[pos] = e;
}

// ---------------- W3 permute: W3p[i, k*64+o] = W3[k, i*64+o] ----------------
__global__ void k_permw3(const float* __restrict__ W3){
    int idx = blockIdx.x*256 + threadIdx.x;        // over 64*16384
    int i = idx >> 14, rem = idx & 16383;
    int k = rem >> 6, o = rem & 63;
    g_W3p[idx] = W3[k*(LDIM*LDIM) + i*LDIM + o];
}

// ---------------- MLP layer 1: h1 = gelu(ea @ W1 + b1) ----------------
__global__ void k_mlp1(const float* __restrict__ ea, const float* __restrict__ W1,
                       const float* __restrict__ b1){
    int idx = blockIdx.x*256 + threadIdx.x;        // E*256 threads
    int e = idx >> 8, k = idx & 255;
    const float* ar = ea + e*EDIM;
    float v = b1[k];
    #pragma unroll
    for (int j=0; j<EDIM; j++) v += ar[j] * W1[j*KDIM + k];
    g_h1[idx] = gelu_f(v);
}

// ---------------- tf32 tensor-core GEMM: C = act(A[M,K] @ B[K,N] + bias) ----------------
#define BMt 128
#define BNt 128
#define BKt 32
#define AST 36     /* As row stride (floats): conflict-free fragment loads */
#define BST 136    /* Bs row stride */

__global__ __launch_bounds__(256) void k_gemm(
    const float* __restrict__ A, const float* __restrict__ B, float* __restrict__ C,
    int M, int N, int K, const float* __restrict__ bias, int do_gelu)
{
    __shared__ float As[BMt*AST];
    __shared__ float Bs[BKt*BST];
    int tid = threadIdx.x;
    int lane = tid & 31, warp = tid >> 5;
    int g = lane >> 2, tg = lane & 3;
    int wm = (warp >> 2) * 64;     // warp rows (2 warp-rows)
    int wn = (warp & 3) * 32;      // warp cols (4 warp-cols)
    size_t bm0 = (size_t)blockIdx.y * BMt;
    size_t bn0 = (size_t)blockIdx.x * BNt;

    float acc[4][4][4];
    #pragma unroll
    for (int a=0;a<4;a++)
        #pragma unroll
        for (int b=0;b<4;b++)
            #pragma unroll
            for (int c=0;c<4;c++) acc[a][b][c] = 0.f;

    for (int k0 = 0; k0 < K; k0 += BKt){
        #pragma unroll
        for (int i = tid; i < BMt*BKt/4; i += 256){
            int r = i >> 3, c4 = i & 7;
            float4 v = *(const float4*)(A + (bm0 + r)*K + k0 + (c4<<2));
            *(float4*)&As[r*AST + (c4<<2)] = v;
        }
        #pragma unroll
        for (int i = tid; i < BKt*BNt/4; i += 256){
            int r = i >> 5, c4 = i & 31;
            float4 v = *(const float4*)(B + (size_t)(k0 + r)*N + bn0 + (c4<<2));
            *(float4*)&Bs[r*BST + (c4<<2)] = v;
        }
        __syncthreads();
        #pragma unroll
        for (int kk = 0; kk < BKt; kk += 8){
            uint32_t af[4][4], bf[4][2];
            #pragma unroll
            for (int mi=0; mi<4; mi++){
                int mr = wm + mi*16;
                af[mi][0] = f2tf(As[(mr+g  )*AST + kk + tg    ]);
                af[mi][1] = f2tf(As[(mr+g+8)*AST + kk + tg    ]);
                af[mi][2] = f2tf(As[(mr+g  )*AST + kk + tg + 4]);
                af[mi][3] = f2tf(As[(mr+g+8)*AST + kk + tg + 4]);
            }
            #pragma unroll
            for (int ni=0; ni<4; ni++){
                int nc = wn + ni*8 + g;
                bf[ni][0] = f2tf(Bs[(kk+tg  )*BST + nc]);
                bf[ni][1] = f2tf(Bs[(kk+tg+4)*BST + nc]);
            }
            #pragma unroll
            for (int mi=0; mi<4; mi++)
                #pragma unroll
                for (int ni=0; ni<4; ni++)
                    mma8(acc[mi][ni], af[mi], bf[ni]);
        }
        __syncthreads();
    }
    // epilogue
    #pragma unroll
    for (int mi=0; mi<4; mi++){
        size_t r0 = bm0 + wm + mi*16 + g;
        #pragma unroll
        for (int ni=0; ni<4; ni++){
            size_t c0 = bn0 + wn + ni*8 + (tg<<1);
            float v0 = acc[mi][ni][0], v1 = acc[mi][ni][1];
            float v2 = acc[mi][ni][2], v3 = acc[mi][ni][3];
            if (bias){
                float bb0 = bias[c0], bb1 = bias[c0+1];
                v0 += bb0; v1 += bb1; v2 += bb0; v3 += bb1;
            }
            if (do_gelu){ v0 = gelu_f(v0); v1 = gelu_f(v1); v2 = gelu_f(v2); v3 = gelu_f(v3); }
            *(float2*)&C[ r0   *N + c0] = make_float2(v0, v1);
            *(float2*)&C[(r0+8)*N + c0] = make_float2(v2, v3);
        }
    }
}

// ---------------- edge stage: per-src-node  msg = h_grp @ P[n] (+x@b3), scatter to dst ----------------
__global__ __launch_bounds__(256) void k_edge(const int* __restrict__ ei){
    __shared__ float hs[16*KDIM];    // 16 KB chunk of h rows
    __shared__ int   earr[16];
    int n = blockIdx.x;
    int t = threadIdx.x;
    int o = t & 63, gq = t >> 6;     // 64 outputs x 4 edge slots
    int start = g_off[n];
    int deg = g_off[n+1] - start;
    if (deg == 0) return;
    float xb3v = g_xb3[n*LDIM + o];
    const float* __restrict__ Pn = g_P + (size_t)n * KL;

    for (int c0 = 0; c0 < deg; c0 += 16){
        int csz = min(16, deg - c0);
        if (t < 16) earr[t] = (t < csz) ? g_csr[start + c0 + t] : 0;
        __syncthreads();
        for (int i = t; i < 16*KDIM; i += 256){
            int slot = i >> 8, k = i & 255;
            hs[i] = (slot < csz) ? g_h[(size_t)earr[slot]*KDIM + k] : 0.f;
        }
        __syncthreads();
        float acc[4] = {0.f, 0.f, 0.f, 0.f};
        #pragma unroll 4
        for (int k = 0; k < KDIM; k++){
            float p = __ldg(&Pn[k*LDIM + o]);
            acc[0] += hs[(gq   )*KDIM + k] * p;
            acc[1] += hs[(gq+ 4)*KDIM + k] * p;
            acc[2] += hs[(gq+ 8)*KDIM + k] * p;
            acc[3] += hs[(gq+12)*KDIM + k] * p;
        }
        #pragma unroll
        for (int j = 0; j < 4; j++){
            int slot = gq + 4*j;
            if (slot < csz){
                int e = earr[slot];
                int d = ei[N_EDGES + e];
                atomicAdd(&g_agg[(size_t)d*LDIM + o], acc[j] + xb3v);
            }
        }
        __syncthreads();
    }
}

// ---------------- small node matmul: out = x @ W64 (+agg +bias, opt gelu) ----------------
__global__ __launch_bounds__(256) void k_nodemat(
    const float* __restrict__ x, const float* __restrict__ W,
    const float* __restrict__ agg, const float* __restrict__ bias,
    float* __restrict__ out, int do_gelu)
{
    __shared__ float xs[4*LDIM];
    int t = threadIdx.x;
    int o = t & 63, loc = t >> 6;
    int n0 = blockIdx.x * 4;
    xs[t] = x[(size_t)n0*LDIM + t];
    __syncthreads();
    int n = n0 + loc;
    float v = 0.f;
    #pragma unroll 8
    for (int i = 0; i < LDIM; i++) v += xs[loc*LDIM + i] * __ldg(&W[i*LDIM + o]);
    if (agg)  v += agg[(size_t)n*LDIM + o];
    if (bias) v += bias[o];
    if (do_gelu) v = gelu_f(v);
    out[(size_t)n*LDIM + o] = v;
}

// ---------------- launch ----------------
extern "C" void kernel_launch(void* const* d_in, const int* in_sizes, int n_in,
                              void* d_out, int out_size)
{
    const float* nodes = (const float*)d_in[0];
    const int*   ei    = (const int*)  d_in[1];
    const float* ea    = (const float*)d_in[2];
    const float* W1    = (const float*)d_in[3];
    const float* b1    = (const float*)d_in[4];
    const float* W2    = (const float*)d_in[5];
    const float* b2    = (const float*)d_in[6];
    const float* W3    = (const float*)d_in[7];
    const float* b3    = (const float*)d_in[8];
    const float* Wr    = (const float*)d_in[9];
    const float* bias  = (const float*)d_in[10];
    float* out = (float*)d_out;

    float *pW3p, *pH1, *pH, *pP, *pX1, *pXb3, *pAgg;
    cudaGetSymbolAddress((void**)&pW3p, g_W3p);
    cudaGetSymbolAddress((void**)&pH1,  g_h1);
    cudaGetSymbolAddress((void**)&pH,   g_h);
    cudaGetSymbolAddress((void**)&pP,   g_P);
    cudaGetSymbolAddress((void**)&pX1,  g_x1);
    cudaGetSymbolAddress((void**)&pXb3, g_xb3);
    cudaGetSymbolAddress((void**)&pAgg, g_agg);

    // CSR + constants prep
    k_init   <<<N_NODES*LDIM/256, 256>>>();
    k_deg    <<<N_EDGES/256, 256>>>(ei);
    k_scan   <<<1, 1024>>>();
    k_fill   <<<N_EDGES/256, 256>>>(ei);
    k_permw3 <<<(LDIM*KL)/256, 256>>>(W3);

    // edge MLP (shared by both convs): h = gelu(gelu(ea@W1+b1)@W2+b2)
    k_mlp1 <<<N_EDGES, 256>>>(ea, W1, b1);
    k_gemm <<<dim3(KDIM/BNt, N_EDGES/BMt), 256>>>(pH1, W2, pH, N_EDGES, KDIM, KDIM, b2, 1);

    // ---- conv 1 (x = nodes) ----
    k_gemm    <<<dim3(KL/BNt, N_NODES/BMt), 256>>>(nodes, pW3p, pP, N_NODES, KL, LDIM, nullptr, 0);
    k_nodemat <<<N_NODES/4, 256>>>(nodes, b3, nullptr, nullptr, pXb3, 0);
    k_edge    <<<N_NODES, 256>>>(ei);
    k_nodemat <<<N_NODES/4, 256>>>(nodes, Wr, pAgg, bias, pX1, 1);   // + gelu
    k_zero_agg<<<N_NODES*LDIM/256, 256>>>();

    // ---- conv 2 (x = x1) ----
    k_gemm    <<<dim3(KL/BNt, N_NODES/BMt), 256>>>(pX1, pW3p, pP, N_NODES, KL, LDIM, nullptr, 0);
    k_nodemat <<<N_NODES/4, 256>>>(pX1, b3, nullptr, nullptr, pXb3, 0);
    k_edge    <<<N_NODES, 256>>>(ei);
    k_nodemat <<<N_NODES/4, 256>>>(pX1, Wr, pAgg, bias, out, 0);     // no gelu
}

// round 3
// speedup vs baseline: 1.1296x; 1.1296x over previous
#include <cuda_runtime.h>
#include <cstdint>

#define N_NODES 4096
#define N_EDGES 65536
#define LDIM 64
#define KDIM 256
#define EDIM 6
#define KL (KDIM*LDIM)   /* 16384 */

// ---------------- scratch (device globals; no runtime allocation) ----------------
__device__ float g_W3p[LDIM*KL];                 // permuted W3: [i][k*64+o]  (4 MB)
__device__ float g_h [(size_t)N_EDGES*KDIM];     // 64 MB (tf32-truncated)
__device__ float g_P [(size_t)N_NODES*KL];       // 256 MB (tf32-truncated)
__device__ float g_x1 [N_NODES*LDIM];
__device__ float g_xb3[N_NODES*LDIM];
__device__ float g_agg [N_NODES*LDIM];
__device__ float g_agg2[N_NODES*LDIM];
__device__ int   g_deg[N_NODES];
__device__ int   g_off[N_NODES+1];
__device__ int   g_cur[N_NODES];
__device__ int   g_csr[N_EDGES];

// ---------------- helpers ----------------
__device__ __forceinline__ float gelu_f(float x){
    return 0.5f * x * (1.0f + erff(x * 0.70710678118654752440f));
}
__device__ __forceinline__ uint32_t f2tf(float x){
    uint32_t u; asm("cvt.rna.tf32.f32 %0, %1;" : "=r"(u) : "f"(x)); return u;
}
__device__ __forceinline__ float trunc_tf(float x){
    return __uint_as_float(f2tf(x));
}
__device__ __forceinline__ void mma8(float* c, const uint32_t* a, const uint32_t* b){
    asm volatile(
        "mma.sync.aligned.m16n8k8.row.col.f32.tf32.tf32.f32 "
        "{%0,%1,%2,%3}, {%4,%5,%6,%7}, {%8,%9}, {%0,%1,%2,%3};\n"
        : "+f"(c[0]), "+f"(c[1]), "+f"(c[2]), "+f"(c[3])
        : "r"(a[0]), "r"(a[1]), "r"(a[2]), "r"(a[3]), "r"(b[0]), "r"(b[1]));
}

// ---------------- init / CSR build ----------------
__global__ void k_init(){
    int idx = blockIdx.x*256 + threadIdx.x;        // 262144 threads
    g_agg[idx]  = 0.f;
    g_agg2[idx] = 0.f;
    if (idx < N_NODES) g_deg[idx] = 0;
}
__global__ void k_deg(const int* __restrict__ ei){
    int e = blockIdx.x*256 + threadIdx.x;
    atomicAdd(&g_deg[ei[e]], 1);
}
__global__ void k_scan(){                          // 1 block, 1024 threads, 4 elems each
    __shared__ int wsum[32];
    int t = threadIdx.x, lane = t & 31, w = t >> 5;
    int d0 = g_deg[t*4+0], d1 = g_deg[t*4+1], d2 = g_deg[t*4+2], d3 = g_deg[t*4+3];
    int s0 = d0, s1 = s0+d1, s2 = s1+d2, s3 = s2+d3;
    int tot = s3;
    int v = tot;
    #pragma unroll
    for (int off=1; off<32; off<<=1){ int u = __shfl_up_sync(0xffffffffu, v, off); if (lane>=off) v += u; }
    if (lane == 31) wsum[w] = v;
    __syncthreads();
    if (w == 0){
        int s = wsum[lane];
        #pragma unroll
        for (int off=1; off<32; off<<=1){ int u = __shfl_up_sync(0xffffffffu, s, off); if (lane>=off) s += u; }
        wsum[lane] = s;
    }
    __syncthreads();
    int base = v - tot + (w ? wsum[w-1] : 0);
    g_off[t*4+0] = base;      g_cur[t*4+0] = base;
    g_off[t*4+1] = base+s0;   g_cur[t*4+1] = base+s0;
    g_off[t*4+2] = base+s1;   g_cur[t*4+2] = base+s1;
    g_off[t*4+3] = base+s2;   g_cur[t*4+3] = base+s2;
    if (t == 1023) g_off[N_NODES] = base + tot;
}
__global__ void k_fill(const int* __restrict__ ei){
    int e = blockIdx.x*256 + threadIdx.x;
    int s = ei[e];
    int pos = atomicAdd(&g_cur[s], 1);
    g_csr[pos] = e;
}

// ---------------- W3 permute: W3p[i, k*64+o] = W3[k, i*64+o] ----------------
__global__ void k_permw3(const float* __restrict__ W3){
    int idx = blockIdx.x*256 + threadIdx.x;        // over 64*16384
    int i = idx >> 14, rem = idx & 16383;
    int k = rem >> 6, o = rem & 63;
    g_W3p[idx] = W3[k*(LDIM*LDIM) + i*LDIM + o];
}

// ---------------- tf32 GEMM for P: P = x @ W3p, tf32-truncated store ----------------
#define BMt 128
#define BNt 128
#define BKt 32
#define AST 36
#define BST 136

__global__ __launch_bounds__(256) void k_gemmP(
    const float* __restrict__ A, float* __restrict__ C, int N, int K)
{
    __shared__ float As[BMt*AST];
    __shared__ float Bs[BKt*BST];
    const float* __restrict__ B = g_W3p;
    int tid = threadIdx.x;
    int lane = tid & 31, warp = tid >> 5;
    int g = lane >> 2, tg = lane & 3;
    int wm = (warp >> 2) * 64;
    int wn = (warp & 3) * 32;
    size_t bm0 = (size_t)blockIdx.y * BMt;
    size_t bn0 = (size_t)blockIdx.x * BNt;

    float acc[4][4][4];
    #pragma unroll
    for (int a=0;a<4;a++)
        #pragma unroll
        for (int b=0;b<4;b++)
            #pragma unroll
            for (int c=0;c<4;c++) acc[a][b][c] = 0.f;

    for (int k0 = 0; k0 < K; k0 += BKt){
        #pragma unroll
        for (int i = tid; i < BMt*BKt/4; i += 256){
            int r = i >> 3, c4 = i & 7;
            float4 v = *(const float4*)(A + (bm0 + r)*K + k0 + (c4<<2));
            *(float4*)&As[r*AST + (c4<<2)] = v;
        }
        #pragma unroll
        for (int i = tid; i < BKt*BNt/4; i += 256){
            int r = i >> 5, c4 = i & 31;
            float4 v = *(const float4*)(B + (size_t)(k0 + r)*N + bn0 + (c4<<2));
            *(float4*)&Bs[r*BST + (c4<<2)] = v;
        }
        __syncthreads();
        #pragma unroll
        for (int kk = 0; kk < BKt; kk += 8){
            uint32_t af[4][4], bf[4][2];
            #pragma unroll
            for (int mi=0; mi<4; mi++){
                int mr = wm + mi*16;
                af[mi][0] = f2tf(As[(mr+g  )*AST + kk + tg    ]);
                af[mi][1] = f2tf(As[(mr+g+8)*AST + kk + tg    ]);
                af[mi][2] = f2tf(As[(mr+g  )*AST + kk + tg + 4]);
                af[mi][3] = f2tf(As[(mr+g+8)*AST + kk + tg + 4]);
            }
            #pragma unroll
            for (int ni=0; ni<4; ni++){
                int nc = wn + ni*8 + g;
                bf[ni][0] = f2tf(Bs[(kk+tg  )*BST + nc]);
                bf[ni][1] = f2tf(Bs[(kk+tg+4)*BST + nc]);
            }
            #pragma unroll
            for (int mi=0; mi<4; mi++)
                #pragma unroll
                for (int ni=0; ni<4; ni++)
                    mma8(acc[mi][ni], af[mi], bf[ni]);
        }
        __syncthreads();
    }
    #pragma unroll
    for (int mi=0; mi<4; mi++){
        size_t r0 = bm0 + wm + mi*16 + g;
        #pragma unroll
        for (int ni=0; ni<4; ni++){
            size_t c0 = bn0 + wn + ni*8 + (tg<<1);
            *(float2*)&C[ r0   *N + c0] = make_float2(trunc_tf(acc[mi][ni][0]), trunc_tf(acc[mi][ni][1]));
            *(float2*)&C[(r0+8)*N + c0] = make_float2(trunc_tf(acc[mi][ni][2]), trunc_tf(acc[mi][ni][3]));
        }
    }
}

// ---------------- fused h GEMM: h = gelu( gelu(ea@W1+b1) @ W2 + b2 ), tf32 store ----------------
// M=E, N=256, K=256. A-tile (h1) computed on the fly in smem.
__global__ __launch_bounds__(256) void k_hgemm(
    const float* __restrict__ ea, const float* __restrict__ W1, const float* __restrict__ b1,
    const float* __restrict__ W2, const float* __restrict__ b2)
{
    __shared__ float As[BMt*AST];          // 18 KB
    __shared__ float Bs[BKt*BST];          // 17.4 KB
    __shared__ float eas[BMt*EDIM];        // 3 KB
    __shared__ float W1s[EDIM*KDIM];       // 6 KB
    __shared__ float b1s[KDIM];            // 1 KB
    const int Nn = KDIM;
    int tid = threadIdx.x;
    int lane = tid & 31, warp = tid >> 5;
    int g = lane >> 2, tg = lane & 3;
    int wm = (warp >> 2) * 64;
    int wn = (warp & 3) * 32;
    size_t bm0 = (size_t)blockIdx.y * BMt;
    size_t bn0 = (size_t)blockIdx.x * BNt;

    // stage ea rows + W1 + b1
    for (int i = tid; i < BMt*EDIM; i += 256) eas[i] = ea[bm0*EDIM + i];
    for (int i = tid; i < EDIM*KDIM; i += 256) W1s[i] = W1[i];
    if (tid < KDIM) b1s[tid] = b1[tid];

    float acc[4][4][4];
    #pragma unroll
    for (int a=0;a<4;a++)
        #pragma unroll
        for (int b=0;b<4;b++)
            #pragma unroll
            for (int c=0;c<4;c++) acc[a][b][c] = 0.f;

    __syncthreads();

    for (int k0 = 0; k0 < KDIM; k0 += BKt){
        // compute h1 tile [128 x 32] into As
        {
            int c = tid & 31;          // k-col within tile
            int rg = tid >> 5;         // row group (16 rows)
            float w0 = W1s[0*KDIM + k0 + c], w1 = W1s[1*KDIM + k0 + c];
            float w2 = W1s[2*KDIM + k0 + c], w3 = W1s[3*KDIM + k0 + c];
            float w4 = W1s[4*KDIM + k0 + c], w5 = W1s[5*KDIM + k0 + c];
            float bb = b1s[k0 + c];
            #pragma unroll
            for (int i = 0; i < 16; i++){
                int r = rg*16 + i;
                const float* er = &eas[r*EDIM];
                float v = bb + er[0]*w0 + er[1]*w1 + er[2]*w2 + er[3]*w3 + er[4]*w4 + er[5]*w5;
                As[r*AST + c] = gelu_f(v);
            }
        }
        #pragma unroll
        for (int i = tid; i < BKt*BNt/4; i += 256){
            int r = i >> 5, c4 = i & 31;
            float4 v = *(const float4*)(W2 + (size_t)(k0 + r)*Nn + bn0 + (c4<<2));
            *(float4*)&Bs[r*BST + (c4<<2)] = v;
        }
        __syncthreads();
        #pragma unroll
        for (int kk = 0; kk < BKt; kk += 8){
            uint32_t af[4][4], bf[4][2];
            #pragma unroll
            for (int mi=0; mi<4; mi++){
                int mr = wm + mi*16;
                af[mi][0] = f2tf(As[(mr+g  )*AST + kk + tg    ]);
                af[mi][1] = f2tf(As[(mr+g+8)*AST + kk + tg    ]);
                af[mi][2] = f2tf(As[(mr+g  )*AST + kk + tg + 4]);
                af[mi][3] = f2tf(As[(mr+g+8)*AST + kk + tg + 4]);
            }
            #pragma unroll
            for (int ni=0; ni<4; ni++){
                int nc = wn + ni*8 + g;
                bf[ni][0] = f2tf(Bs[(kk+tg  )*BST + nc]);
                bf[ni][1] = f2tf(Bs[(kk+tg+4)*BST + nc]);
            }
            #pragma unroll
            for (int mi=0; mi<4; mi++)
                #pragma unroll
                for (int ni=0; ni<4; ni++)
                    mma8(acc[mi][ni], af[mi], bf[ni]);
        }
        __syncthreads();
    }
    #pragma unroll
    for (int mi=0; mi<4; mi++){
        size_t r0 = bm0 + wm + mi*16 + g;
        #pragma unroll
        for (int ni=0; ni<4; ni++){
            size_t c0 = bn0 + wn + ni*8 + (tg<<1);
            float bb0 = b2[c0], bb1 = b2[c0+1];
            float v0 = gelu_f(acc[mi][ni][0] + bb0);
            float v1 = gelu_f(acc[mi][ni][1] + bb1);
            float v2 = gelu_f(acc[mi][ni][2] + bb0);
            float v3 = gelu_f(acc[mi][ni][3] + bb1);
            *(float2*)&g_h[ r0   *KDIM + c0] = make_float2(trunc_tf(v0), trunc_tf(v1));
            *(float2*)&g_h[(r0+8)*KDIM + c0] = make_float2(trunc_tf(v2), trunc_tf(v3));
        }
    }
}

// ---------------- tensor-core edge stage ----------------
// Per node n: msg[16chunk, 64] = H[16,256] @ P_n[256,64] via mma.m16n8k8.tf32,
// + xb3[n], atomic scatter to agg[dst].
#define PS_ST 68       /* Ps row stride (uint32): conflict-free B frags + 16B align */
#define HS_ST 260      /* hs row stride */
#define EDGE_SMEM ((KDIM*PS_ST + 16*HS_ST)*4 + LDIM*4 + 16*4 + 16*4)

__global__ __launch_bounds__(128) void k_edge(const int* __restrict__ ei,
                                              float* __restrict__ agg)
{
    extern __shared__ uint32_t sm[];
    uint32_t* Ps   = sm;                         // [256][68]
    uint32_t* hs   = sm + KDIM*PS_ST;            // [16][260]
    float*    xb3s = (float*)(hs + 16*HS_ST);    // [64]
    int*      earr = (int*)(xb3s + LDIM);        // [16]
    int*      dsts = earr + 16;                  // [16]

    int n = blockIdx.x;
    int start = g_off[n];
    int deg   = g_off[n+1] - start;
    if (deg == 0) return;

    int t = threadIdx.x;
    int lane = t & 31, warp = t >> 5;
    int g = lane >> 2, tg = lane & 3;
    int n0 = warp * 16;

    // load P_n (tf32 bit patterns) into padded smem
    const float4* Pn = (const float4*)(g_P + (size_t)n * KL);
    #pragma unroll
    for (int i = t; i < KL/4; i += 128){
        float4 v = Pn[i];
        int k = i >> 4, o = (i & 15) << 2;
        *(uint4*)&Ps[k*PS_ST + o] = *(uint4*)&v;
    }
    if (t < LDIM) xb3s[t] = g_xb3[n*LDIM + t];

    for (int c0 = 0; c0 < deg; c0 += 16){
        int csz = min(16, deg - c0);
        __syncthreads();                       // Ps ready / prev epilogue done
        if (t < 16){
            int e = (t < csz) ? g_csr[start + c0 + t] : g_csr[start];
            earr[t] = e;
            dsts[t] = ei[N_EDGES + e];
        }
        __syncthreads();
        // stage h chunk [16 x 256]
        #pragma unroll
        for (int i = t; i < 16*KDIM/4; i += 128){
            int slot = i >> 6, k4 = (i & 63) << 2;
            float4 v = *(const float4*)(g_h + (size_t)earr[slot]*KDIM + k4);
            *(uint4*)&hs[slot*HS_ST + k4] = *(uint4*)&v;
        }
        __syncthreads();

        float acc[2][4] = {{0,0,0,0},{0,0,0,0}};
        #pragma unroll
        for (int ks = 0; ks < KDIM; ks += 8){
            uint32_t a[4];
            a[0] = hs[ g   *HS_ST + ks + tg    ];
            a[1] = hs[(g+8)*HS_ST + ks + tg    ];
            a[2] = hs[ g   *HS_ST + ks + tg + 4];
            a[3] = hs[(g+8)*HS_ST + ks + tg + 4];
            #pragma unroll
            for (int j = 0; j < 2; j++){
                uint32_t b[2];
                int nc = n0 + 8*j + g;
                b[0] = Ps[(ks+tg  )*PS_ST + nc];
                b[1] = Ps[(ks+tg+4)*PS_ST + nc];
                mma8(acc[j], a, b);
            }
        }
        // scatter
        #pragma unroll
        for (int j = 0; j < 2; j++){
            int c = n0 + 8*j + (tg<<1);
            float x0 = xb3s[c], x1 = xb3s[c+1];
            if (g < csz){
                int d = dsts[g];
                atomicAdd(&agg[(size_t)d*LDIM + c    ], acc[j][0] + x0);
                atomicAdd(&agg[(size_t)d*LDIM + c + 1], acc[j][1] + x1);
            }
            if (g + 8 < csz){
                int d = dsts[g+8];
                atomicAdd(&agg[(size_t)d*LDIM + c    ], acc[j][2] + x0);
                atomicAdd(&agg[(size_t)d*LDIM + c + 1], acc[j][3] + x1);
            }
        }
    }
}

// ---------------- small node matmul: out = x @ W64 (+agg +bias, opt gelu) ----------------
__global__ __launch_bounds__(256) void k_nodemat(
    const float* __restrict__ x, const float* __restrict__ W,
    const float* __restrict__ agg, const float* __restrict__ bias,
    float* __restrict__ out, int do_gelu)
{
    __shared__ float xs[4*LDIM];
    int t = threadIdx.x;
    int o = t & 63, loc = t >> 6;
    int n0 = blockIdx.x * 4;
    xs[t] = x[(size_t)n0*LDIM + t];
    __syncthreads();
    int n = n0 + loc;
    float v = 0.f;
    #pragma unroll 8
    for (int i = 0; i < LDIM; i++) v += xs[loc*LDIM + i] * __ldg(&W[i*LDIM + o]);
    if (agg)  v += agg[(size_t)n*LDIM + o];
    if (bias) v += bias[o];
    if (do_gelu) v = gelu_f(v);
    out[(size_t)n*LDIM + o] = v;
}

// ---------------- launch ----------------
extern "C" void kernel_launch(void* const* d_in, const int* in_sizes, int n_in,
                              void* d_out, int out_size)
{
    const float* nodes = (const float*)d_in[0];
    const int*   ei    = (const int*)  d_in[1];
    const float* ea    = (const float*)d_in[2];
    const float* W1    = (const float*)d_in[3];
    const float* b1    = (const float*)d_in[4];
    const float* W2    = (const float*)d_in[5];
    const float* b2    = (const float*)d_in[6];
    const float* W3    = (const float*)d_in[7];
    const float* b3    = (const float*)d_in[8];
    const float* Wr    = (const float*)d_in[9];
    const float* bias  = (const float*)d_in[10];
    float* out = (float*)d_out;

    float *pP, *pX1, *pXb3, *pAgg, *pAgg2;
    cudaGetSymbolAddress((void**)&pP,    g_P);
    cudaGetSymbolAddress((void**)&pX1,   g_x1);
    cudaGetSymbolAddress((void**)&pXb3,  g_xb3);
    cudaGetSymbolAddress((void**)&pAgg,  g_agg);
    cudaGetSymbolAddress((void**)&pAgg2, g_agg2);

    static int smem_set = 0;
    if (!smem_set){
        cudaFuncSetAttribute(k_edge, cudaFuncAttributeMaxDynamicSharedMemorySize, EDGE_SMEM);
        smem_set = 1;
    }

    k_permw3 <<<(LDIM*KL)/256, 256>>>(W3);                                        // 0
    k_init   <<<N_NODES*LDIM/256, 256>>>();                                       // 1
    k_deg    <<<N_EDGES/256, 256>>>(ei);                                          // 2
    k_gemmP  <<<dim3(KL/BNt, N_NODES/BMt), 256>>>(nodes, pP, KL, LDIM);           // 3
    k_scan   <<<1, 1024>>>();                                                     // 4
    k_hgemm  <<<dim3(KDIM/BNt, N_EDGES/BMt), 256>>>(ea, W1, b1, W2, b2);          // 5
    k_fill   <<<N_EDGES/256, 256>>>(ei);                                          // 6
    k_nodemat<<<N_NODES/4, 256>>>(nodes, b3, nullptr, nullptr, pXb3, 0);          // 7

    // ---- conv 1 ----
    k_edge   <<<N_NODES, 128, EDGE_SMEM>>>(ei, pAgg);                             // 8
    k_nodemat<<<N_NODES/4, 256>>>(nodes, Wr, pAgg, bias, pX1, 1);                 // 9

    // ---- conv 2 ----
    k_gemmP  <<<dim3(KL/BNt, N_NODES/BMt), 256>>>(pX1, pP, KL, LDIM);             // 10
    k_nodemat<<<N_NODES/4, 256>>>(pX1, b3, nullptr, nullptr, pXb3, 0);            // 11
    k_edge   <<<N_NODES, 128, EDGE_SMEM>>>(ei, pAgg2);                            // 12
    k_nodemat<<<N_NODES/4, 256>>>(pX1, Wr, pAgg2, bias, out, 0);                  // 13
}